// round 8
// baseline (speedup 1.0000x reference)
#include <cuda_runtime.h>
#include <cuda_fp16.h>
#include <math.h>

#define NNODES 100000
#define NEDGES 1600000
#define FIN 128
#define FOUT 64
#define SCAN_NB ((NNODES + 1023) / 1024)   // 98

typedef unsigned int u32;
typedef unsigned long long u64;

// ---------------- scratch (device globals; 16B-aligned) ----------------
__device__ __align__(16) int     g_ecnt[NNODES];
__device__ __align__(16) int     g_incl[NNODES];
__device__ __align__(16) int     g_bsum[SCAN_NB];
__device__ __align__(16) int     g_rowptr[NNODES + 1];
__device__ __align__(16) int     g_cursor[NNODES];
__device__ __align__(16) int     g_col[NEDGES];
__device__ __align__(16) float   g_dinv[NNODES];
__device__ __align__(16) __half2 g_h[NNODES * (FOUT / 2)];   // (x@W)*dinv, fp16 gather table
__device__ __align__(16) float   g_t1[NNODES * FOUT];        // x_temp (residual, fp32)
__device__ __align__(16) float   g_t2[NNODES * FOUT];        // layer-2 activation (fp32)
__device__ int g_is64;

// packed fp32x2 FMA: acc = a*b + acc  (Blackwell FFMA2; full fp32 precision)
__device__ __forceinline__ void ffma2(u64& acc, u64 a, u64 b) {
    asm("fma.rn.f32x2 %0, %1, %2, %0;" : "+l"(acc) : "l"(a), "l"(b));
}

// ---------------- dtype detector ----------------
__global__ void k_detect(const void* __restrict__ ei) {
    const unsigned long long* p = (const unsigned long long*)ei;
    __shared__ unsigned int s;
    if (threadIdx.x == 0) s = 0u;
    __syncthreads();
    unsigned int any = 0u;
    for (int i = threadIdx.x; i < 4096; i += 256)
        any |= (unsigned int)(p[i] >> 32);
    atomicOr(&s, any);
    __syncthreads();
    if (threadIdx.x == 0) g_is64 = (s == 0u) ? 1 : 0;
}

__device__ __forceinline__ int load_idx(const int* __restrict__ ei32, long long pos) {
    if (g_is64) return (int)((const long long*)ei32)[pos];
    return ei32[pos];
}

// ---------------- CSR build ----------------
__global__ void k_zero() {
    int i = blockIdx.x * blockDim.x + threadIdx.x;
    if (i < NNODES) g_ecnt[i] = 0;
}

__global__ void k_count(const int* __restrict__ ei32) {
    int e = blockIdx.x * blockDim.x + threadIdx.x;
    if (e < NEDGES) {
        int d = load_idx(ei32, (long long)NEDGES + e);
        if ((unsigned)d < (unsigned)NNODES) atomicAdd(&g_ecnt[d], 1);
    }
}

__global__ __launch_bounds__(1024) void k_scan1() {
    __shared__ int wsum[32];
    const int i    = blockIdx.x * 1024 + threadIdx.x;
    const int lane = threadIdx.x & 31;
    const int warp = threadIdx.x >> 5;
    int v = (i < NNODES) ? g_ecnt[i] : 0;
    int x = v;
#pragma unroll
    for (int o = 1; o < 32; o <<= 1) {
        int y = __shfl_up_sync(0xffffffffu, x, o);
        if (lane >= o) x += y;
    }
    if (lane == 31) wsum[warp] = x;
    __syncthreads();
    if (warp == 0) {
        int s = wsum[lane];
#pragma unroll
        for (int o = 1; o < 32; o <<= 1) {
            int y = __shfl_up_sync(0xffffffffu, s, o);
            if (lane >= o) s += y;
        }
        wsum[lane] = s;
    }
    __syncthreads();
    int incl = x + (warp > 0 ? wsum[warp - 1] : 0);
    if (i < NNODES) g_incl[i] = incl;
    if (threadIdx.x == 1023) g_bsum[blockIdx.x] = incl;
}

__global__ void k_scan2() {
    __shared__ int s[128];
    const int t = threadIdx.x;
    s[t] = (t < SCAN_NB) ? g_bsum[t] : 0;
    __syncthreads();
    for (int o = 1; o < 128; o <<= 1) {
        int x = s[t];
        int add = (t >= o) ? s[t - o] : 0;
        __syncthreads();
        s[t] = x + add;
        __syncthreads();
    }
    if (t < SCAN_NB) g_bsum[t] = (t == 0) ? 0 : s[t - 1];
    if (t == 0) g_rowptr[NNODES] = s[SCAN_NB - 1];
}

__global__ __launch_bounds__(1024) void k_scan3() {
    const int i = blockIdx.x * 1024 + threadIdx.x;
    if (i < NNODES) {
        int c = g_ecnt[i];
        int start = g_bsum[blockIdx.x] + g_incl[i] - c;
        g_rowptr[i] = start;
        g_cursor[i] = start;
        g_dinv[i]   = rsqrtf((float)(c + 1));
    }
}

__global__ void k_fill(const int* __restrict__ ei32) {
    int e = blockIdx.x * blockDim.x + threadIdx.x;
    if (e < NEDGES) {
        int d = load_idx(ei32, (long long)NEDGES + e);
        int s = load_idx(ei32, e);
        if ((unsigned)d < (unsigned)NNODES && (unsigned)s < (unsigned)NNODES) {
            int p = atomicAdd(&g_cursor[d], 1);
            g_col[p] = s;
        }
    }
}

// ---------------- GEMM: g_h[n,:] = half((X[n,:] @ W) * dinv[n]) ----------------
// 256 threads = 8 warps, 4 nodes/warp -> 32 nodes/block. K chunked by 64.
// X tile stored DUPLICATED (v,v) so the inner loop is pure LDS.64 + FFMA2.
// SEL: 0 = external X, 1 = g_t1, 2 = g_t2 (compile-time only).
template <int K, int SEL>
__global__ __launch_bounds__(256) void k_gemm(const float* __restrict__ Xext,
                                              const float* __restrict__ W) {
    __shared__ __align__(16) float  wsm[64 * FOUT];    // 16 KB, float2 per lane pair
    __shared__ __align__(16) float2 xsm[32 * 64];      // 16 KB, (v,v) duplicated

    const float* X;
    if constexpr (SEL == 0)      X = Xext;
    else if constexpr (SEL == 1) X = g_t1;
    else                         X = g_t2;

    const int tid  = threadIdx.x;
    const int warp = tid >> 5;
    const int lane = tid & 31;
    const int base = blockIdx.x * 32;               // NNODES % 32 == 0

    u64 a0 = 0ull, a1 = 0ull, a2 = 0ull, a3 = 0ull;

#pragma unroll
    for (int kc = 0; kc < K; kc += 64) {
        for (int i = tid; i < 64 * FOUT; i += 256)
            wsm[i] = W[kc * FOUT + i];
        for (int i = tid; i < 32 * 64; i += 256) {
            int r = i >> 6, c = i & 63;
            float v = X[(size_t)(base + r) * K + kc + c];
            xsm[i] = make_float2(v, v);
        }
        __syncthreads();

        const u64* x0 = (const u64*)&xsm[(warp * 4 + 0) * 64];
        const u64* x1 = (const u64*)&xsm[(warp * 4 + 1) * 64];
        const u64* x2 = (const u64*)&xsm[(warp * 4 + 2) * 64];
        const u64* x3 = (const u64*)&xsm[(warp * 4 + 3) * 64];

#pragma unroll 8
        for (int k = 0; k < 64; k++) {
            u64 w = *(const u64*)&wsm[k * FOUT + 2 * lane];
            ffma2(a0, x0[k], w);
            ffma2(a1, x1[k], w);
            ffma2(a2, x2[k], w);
            ffma2(a3, x3[k], w);
        }
        __syncthreads();
    }

    const int n0 = base + warp * 4;
    const float s0 = g_dinv[n0 + 0], s1 = g_dinv[n0 + 1];
    const float s2 = g_dinv[n0 + 2], s3 = g_dinv[n0 + 3];
    const int hoff = lane;   // half2 column-pair index
    float2 f0 = make_float2(__uint_as_float((u32)a0) * s0, __uint_as_float((u32)(a0 >> 32)) * s0);
    float2 f1 = make_float2(__uint_as_float((u32)a1) * s1, __uint_as_float((u32)(a1 >> 32)) * s1);
    float2 f2 = make_float2(__uint_as_float((u32)a2) * s2, __uint_as_float((u32)(a2 >> 32)) * s2);
    float2 f3 = make_float2(__uint_as_float((u32)a3) * s3, __uint_as_float((u32)(a3 >> 32)) * s3);
    g_h[(size_t)(n0 + 0) * 32 + hoff] = __floats2half2_rn(f0.x, f0.y);
    g_h[(size_t)(n0 + 1) * 32 + hoff] = __floats2half2_rn(f1.x, f1.y);
    g_h[(size_t)(n0 + 2) * 32 + hoff] = __floats2half2_rn(f2.x, f2.y);
    g_h[(size_t)(n0 + 3) * 32 + hoff] = __floats2half2_rn(f3.x, f3.y);
}

// ---------------- aggregation ----------------
// out[i] = f(dinv[i]*(g_h[i] + sum_{src->i} g_h[src]) + bias); g_h is half2.
// MODE 0: identity -> g_t1 | MODE 1: relu -> g_t2 | MODE 2: relu + g_t1 -> ext out
template <int MODE>
__global__ __launch_bounds__(256) void k_agg(const float* __restrict__ bias,
                                             float* __restrict__ outext) {
    const int warp = threadIdx.x >> 5;
    const int lane = threadIdx.x & 31;
    const int node = blockIdx.x * 8 + warp;
    if (node >= NNODES) return;

    float* out;
    if constexpr (MODE == 0)      out = g_t1;
    else if constexpr (MODE == 1) out = g_t2;
    else                          out = outext;

    const int beg = g_rowptr[node];
    const int end = g_rowptr[node + 1];

    float2 acc = __half22float2(g_h[(size_t)node * 32 + lane]);   // self-loop

    int p = beg;
    for (; p + 4 <= end; p += 4) {
        int s0 = g_col[p], s1 = g_col[p + 1], s2 = g_col[p + 2], s3 = g_col[p + 3];
        float2 b0 = __half22float2(g_h[(size_t)s0 * 32 + lane]);
        float2 b1 = __half22float2(g_h[(size_t)s1 * 32 + lane]);
        float2 b2 = __half22float2(g_h[(size_t)s2 * 32 + lane]);
        float2 b3 = __half22float2(g_h[(size_t)s3 * 32 + lane]);
        acc.x += (b0.x + b1.x) + (b2.x + b3.x);
        acc.y += (b0.y + b1.y) + (b2.y + b3.y);
    }
    for (; p < end; p++) {
        int s = g_col[p];
        float2 b = __half22float2(g_h[(size_t)s * 32 + lane]);
        acc.x += b.x; acc.y += b.y;
    }

    const int off = 2 * lane;
    const float di = g_dinv[node];
    float2 bb = *(const float2*)&bias[off];
    float rx = fmaf(di, acc.x, bb.x);
    float ry = fmaf(di, acc.y, bb.y);
    if (MODE >= 1) { rx = fmaxf(rx, 0.f); ry = fmaxf(ry, 0.f); }
    if (MODE == 2) {
        float2 r = *(const float2*)&g_t1[(size_t)node * FOUT + off];
        rx += r.x; ry += r.y;
    }
    *(float2*)&out[(size_t)node * FOUT + off] = make_float2(rx, ry);
}

// ---------------- launch ----------------
extern "C" void kernel_launch(void* const* d_in, const int* in_sizes, int n_in,
                              void* d_out, int out_size) {
    const float* x  = (const float*)d_in[0];
    const int*   ei = (const int*)d_in[1];     // int32 or int64; detected on device
    const float* W0 = (const float*)d_in[2];
    const float* b0 = (const float*)d_in[3];
    const float* Ws = (const float*)d_in[4];
    const float* bs = (const float*)d_in[5];
    float*       out = (float*)d_out;

    const int NB_N = (NNODES + 255) / 256;
    const int NB_E = (NEDGES + 255) / 256;
    const int NB_G = NNODES / 32;            // 3125 (exact)
    const int NB_A = (NNODES + 7) / 8;       // 12500

    // CSR build (per call; deterministic)
    k_detect<<<1, 256>>>(ei);
    k_zero  <<<NB_N, 256>>>();
    k_count <<<NB_E, 256>>>(ei);
    k_scan1 <<<SCAN_NB, 1024>>>();
    k_scan2 <<<1, 128>>>();
    k_scan3 <<<SCAN_NB, 1024>>>();
    k_fill  <<<NB_E, 256>>>(ei);

    // layer 1: t1 = conv(x, W0, b0)
    k_gemm<FIN, 0> <<<NB_G, 256>>>(x, W0);
    k_agg<0>       <<<NB_A, 256>>>(b0, nullptr);

    // layer 2: t2 = relu(conv(t1, Ws[0], bs[0]))
    k_gemm<FOUT, 1><<<NB_G, 256>>>(nullptr, Ws);
    k_agg<1>       <<<NB_A, 256>>>(bs, nullptr);

    // layer 3: out = relu(conv(t2, Ws[1], bs[1])) + t1
    k_gemm<FOUT, 2><<<NB_G, 256>>>(nullptr, Ws + FOUT * FOUT);
    k_agg<2>       <<<NB_A, 256>>>(bs + FOUT, out);
}

// round 9
// speedup vs baseline: 1.1371x; 1.1371x over previous
#include <cuda_runtime.h>
#include <cuda_fp16.h>
#include <math.h>

#define NNODES 100000
#define NEDGES 1600000
#define FIN 128
#define FOUT 64
#define SCAN_NB ((NNODES + 1023) / 1024)   // 98

typedef unsigned int u32;

// ---------------- scratch (device globals; 16B-aligned) ----------------
__device__ __align__(16) int     g_ecnt[NNODES];
__device__ __align__(16) int     g_incl[NNODES];
__device__ __align__(16) int     g_bsum[SCAN_NB];
__device__ __align__(16) int     g_rowptr[NNODES + 1];
__device__ __align__(16) int     g_cursor[NNODES];
__device__ __align__(16) int     g_col[NEDGES];
__device__ __align__(16) float   g_dinv[NNODES];
__device__ __align__(16) __half2 g_h[NNODES * (FOUT / 2)];   // (x@W)*dinv, fp16 gather table
__device__ __align__(16) float   g_t1[NNODES * FOUT];        // x_temp (residual, fp32)
__device__ __align__(16) float   g_t2[NNODES * FOUT];        // layer-2 activation (fp32)
__device__ int g_is64;

// ---------------- dtype detector ----------------
__global__ void k_detect(const void* __restrict__ ei) {
    const unsigned long long* p = (const unsigned long long*)ei;
    __shared__ unsigned int s;
    if (threadIdx.x == 0) s = 0u;
    __syncthreads();
    unsigned int any = 0u;
    for (int i = threadIdx.x; i < 4096; i += 256)
        any |= (unsigned int)(p[i] >> 32);
    atomicOr(&s, any);
    __syncthreads();
    if (threadIdx.x == 0) g_is64 = (s == 0u) ? 1 : 0;
}

__device__ __forceinline__ int load_idx(const int* __restrict__ ei32, long long pos) {
    if (g_is64) return (int)((const long long*)ei32)[pos];
    return ei32[pos];
}

// ---------------- CSR build ----------------
__global__ void k_zero() {
    int i = blockIdx.x * blockDim.x + threadIdx.x;
    if (i < NNODES) g_ecnt[i] = 0;
}

__global__ void k_count(const int* __restrict__ ei32) {
    int e = blockIdx.x * blockDim.x + threadIdx.x;
    if (e < NEDGES) {
        int d = load_idx(ei32, (long long)NEDGES + e);
        if ((unsigned)d < (unsigned)NNODES) atomicAdd(&g_ecnt[d], 1);
    }
}

__global__ __launch_bounds__(1024) void k_scan1() {
    __shared__ int wsum[32];
    const int i    = blockIdx.x * 1024 + threadIdx.x;
    const int lane = threadIdx.x & 31;
    const int warp = threadIdx.x >> 5;
    int v = (i < NNODES) ? g_ecnt[i] : 0;
    int x = v;
#pragma unroll
    for (int o = 1; o < 32; o <<= 1) {
        int y = __shfl_up_sync(0xffffffffu, x, o);
        if (lane >= o) x += y;
    }
    if (lane == 31) wsum[warp] = x;
    __syncthreads();
    if (warp == 0) {
        int s = wsum[lane];
#pragma unroll
        for (int o = 1; o < 32; o <<= 1) {
            int y = __shfl_up_sync(0xffffffffu, s, o);
            if (lane >= o) s += y;
        }
        wsum[lane] = s;
    }
    __syncthreads();
    int incl = x + (warp > 0 ? wsum[warp - 1] : 0);
    if (i < NNODES) g_incl[i] = incl;
    if (threadIdx.x == 1023) g_bsum[blockIdx.x] = incl;
}

__global__ void k_scan2() {
    __shared__ int s[128];
    const int t = threadIdx.x;
    s[t] = (t < SCAN_NB) ? g_bsum[t] : 0;
    __syncthreads();
    for (int o = 1; o < 128; o <<= 1) {
        int x = s[t];
        int add = (t >= o) ? s[t - o] : 0;
        __syncthreads();
        s[t] = x + add;
        __syncthreads();
    }
    if (t < SCAN_NB) g_bsum[t] = (t == 0) ? 0 : s[t - 1];
    if (t == 0) g_rowptr[NNODES] = s[SCAN_NB - 1];
}

__global__ __launch_bounds__(1024) void k_scan3() {
    const int i = blockIdx.x * 1024 + threadIdx.x;
    if (i < NNODES) {
        int c = g_ecnt[i];
        int start = g_bsum[blockIdx.x] + g_incl[i] - c;
        g_rowptr[i] = start;
        g_cursor[i] = start;
        g_dinv[i]   = rsqrtf((float)(c + 1));
    }
}

__global__ void k_fill(const int* __restrict__ ei32) {
    int e = blockIdx.x * blockDim.x + threadIdx.x;
    if (e < NEDGES) {
        int d = load_idx(ei32, (long long)NEDGES + e);
        int s = load_idx(ei32, e);
        if ((unsigned)d < (unsigned)NNODES && (unsigned)s < (unsigned)NNODES) {
            int p = atomicAdd(&g_cursor[d], 1);
            g_col[p] = s;
        }
    }
}

// ---------------- GEMM (R6 proven form): g_h[n,:] = half((X[n,:] @ W) * dinv[n]) ----------------
// 256 threads = 8 warps, 4 nodes/warp -> 32 nodes/block. K chunked by 64.
// SEL: 0 = external X, 1 = g_t1, 2 = g_t2 (compile-time only).
template <int K, int SEL>
__global__ __launch_bounds__(256) void k_gemm(const float* __restrict__ Xext,
                                              const float* __restrict__ W) {
    __shared__ __align__(16) float wsm[64 * FOUT];
    __shared__ __align__(16) float xsm[32 * 64];

    const float* X;
    if constexpr (SEL == 0)      X = Xext;
    else if constexpr (SEL == 1) X = g_t1;
    else                         X = g_t2;

    const int tid  = threadIdx.x;
    const int warp = tid >> 5;
    const int lane = tid & 31;
    const int base = blockIdx.x * 32;               // NNODES % 32 == 0

    float2 a0 = {0.f, 0.f}, a1 = {0.f, 0.f}, a2 = {0.f, 0.f}, a3 = {0.f, 0.f};

#pragma unroll
    for (int kc = 0; kc < K; kc += 64) {
        for (int i = tid; i < 64 * FOUT; i += 256)
            wsm[i] = W[kc * FOUT + i];
        for (int i = tid; i < 32 * 64; i += 256) {
            int r = i >> 6, c = i & 63;
            xsm[i] = X[(size_t)(base + r) * K + kc + c];
        }
        __syncthreads();

        const float* x0 = &xsm[(warp * 4 + 0) * 64];
        const float* x1 = &xsm[(warp * 4 + 1) * 64];
        const float* x2 = &xsm[(warp * 4 + 2) * 64];
        const float* x3 = &xsm[(warp * 4 + 3) * 64];

#pragma unroll 8
        for (int k = 0; k < 64; k++) {
            float2 w = *(const float2*)&wsm[k * FOUT + 2 * lane];
            float v0 = x0[k], v1 = x1[k], v2 = x2[k], v3 = x3[k];
            a0.x = fmaf(v0, w.x, a0.x); a0.y = fmaf(v0, w.y, a0.y);
            a1.x = fmaf(v1, w.x, a1.x); a1.y = fmaf(v1, w.y, a1.y);
            a2.x = fmaf(v2, w.x, a2.x); a2.y = fmaf(v2, w.y, a2.y);
            a3.x = fmaf(v3, w.x, a3.x); a3.y = fmaf(v3, w.y, a3.y);
        }
        __syncthreads();
    }

    const int n0 = base + warp * 4;
    const float s0 = g_dinv[n0 + 0], s1 = g_dinv[n0 + 1];
    const float s2 = g_dinv[n0 + 2], s3 = g_dinv[n0 + 3];
    g_h[(size_t)(n0 + 0) * 32 + lane] = __floats2half2_rn(a0.x * s0, a0.y * s0);
    g_h[(size_t)(n0 + 1) * 32 + lane] = __floats2half2_rn(a1.x * s1, a1.y * s1);
    g_h[(size_t)(n0 + 2) * 32 + lane] = __floats2half2_rn(a2.x * s2, a2.y * s2);
    g_h[(size_t)(n0 + 3) * 32 + lane] = __floats2half2_rn(a3.x * s3, a3.y * s3);
}

// ---------------- aggregation ----------------
// out[i] = f(dinv[i]*(g_h[i] + sum_{src->i} g_h[src]) + bias); g_h is half2.
// MODE 0: identity -> g_t1 | MODE 1: relu -> g_t2 | MODE 2: relu + g_t1 -> ext out
template <int MODE>
__global__ __launch_bounds__(256) void k_agg(const float* __restrict__ bias,
                                             float* __restrict__ outext) {
    const int warp = threadIdx.x >> 5;
    const int lane = threadIdx.x & 31;
    const int node = blockIdx.x * 8 + warp;
    if (node >= NNODES) return;

    float* out;
    if constexpr (MODE == 0)      out = g_t1;
    else if constexpr (MODE == 1) out = g_t2;
    else                          out = outext;

    const int beg = g_rowptr[node];
    const int end = g_rowptr[node + 1];

    float2 acc = __half22float2(g_h[(size_t)node * 32 + lane]);   // self-loop

    int p = beg;
    for (; p + 4 <= end; p += 4) {
        int s0 = g_col[p], s1 = g_col[p + 1], s2 = g_col[p + 2], s3 = g_col[p + 3];
        float2 b0 = __half22float2(g_h[(size_t)s0 * 32 + lane]);
        float2 b1 = __half22float2(g_h[(size_t)s1 * 32 + lane]);
        float2 b2 = __half22float2(g_h[(size_t)s2 * 32 + lane]);
        float2 b3 = __half22float2(g_h[(size_t)s3 * 32 + lane]);
        acc.x += (b0.x + b1.x) + (b2.x + b3.x);
        acc.y += (b0.y + b1.y) + (b2.y + b3.y);
    }
    for (; p < end; p++) {
        int s = g_col[p];
        float2 b = __half22float2(g_h[(size_t)s * 32 + lane]);
        acc.x += b.x; acc.y += b.y;
    }

    const int off = 2 * lane;
    const float di = g_dinv[node];
    float2 bb = *(const float2*)&bias[off];
    float rx = fmaf(di, acc.x, bb.x);
    float ry = fmaf(di, acc.y, bb.y);
    if (MODE >= 1) { rx = fmaxf(rx, 0.f); ry = fmaxf(ry, 0.f); }
    if (MODE == 2) {
        float2 r = *(const float2*)&g_t1[(size_t)node * FOUT + off];
        rx += r.x; ry += r.y;
    }
    *(float2*)&out[(size_t)node * FOUT + off] = make_float2(rx, ry);
}

// ---------------- launch ----------------
extern "C" void kernel_launch(void* const* d_in, const int* in_sizes, int n_in,
                              void* d_out, int out_size) {
    const float* x  = (const float*)d_in[0];
    const int*   ei = (const int*)d_in[1];     // int32 or int64; detected on device
    const float* W0 = (const float*)d_in[2];
    const float* b0 = (const float*)d_in[3];
    const float* Ws = (const float*)d_in[4];
    const float* bs = (const float*)d_in[5];
    float*       out = (float*)d_out;

    const int NB_N = (NNODES + 255) / 256;
    const int NB_E = (NEDGES + 255) / 256;
    const int NB_G = NNODES / 32;            // 3125 (exact)
    const int NB_A = (NNODES + 7) / 8;       // 12500

    // CSR build (per call; deterministic)
    k_detect<<<1, 256>>>(ei);
    k_zero  <<<NB_N, 256>>>();
    k_count <<<NB_E, 256>>>(ei);
    k_scan1 <<<SCAN_NB, 1024>>>();
    k_scan2 <<<1, 128>>>();
    k_scan3 <<<SCAN_NB, 1024>>>();
    k_fill  <<<NB_E, 256>>>(ei);

    // layer 1: t1 = conv(x, W0, b0)
    k_gemm<FIN, 0> <<<NB_G, 256>>>(x, W0);
    k_agg<0>       <<<NB_A, 256>>>(b0, nullptr);

    // layer 2: t2 = relu(conv(t1, Ws[0], bs[0]))
    k_gemm<FOUT, 1><<<NB_G, 256>>>(nullptr, Ws);
    k_agg<1>       <<<NB_A, 256>>>(bs, nullptr);

    // layer 3: out = relu(conv(t2, Ws[1], bs[1])) + t1
    k_gemm<FOUT, 2><<<NB_G, 256>>>(nullptr, Ws + FOUT * FOUT);
    k_agg<2>       <<<NB_A, 256>>>(bs + FOUT, out);
}

// round 10
// speedup vs baseline: 1.2655x; 1.1129x over previous
#include <cuda_runtime.h>
#include <cuda_fp16.h>
#include <math.h>

#define NNODES 100000
#define NEDGES 1600000
#define FIN 128
#define FOUT 64
#define SCAN_NB ((NNODES + 1023) / 1024)   // 98
#define ASTR 72                             // smem row stride in halfs (bank-conflict-free)

typedef unsigned int u32;

// ---------------- scratch (device globals; 16B-aligned) ----------------
__device__ __align__(16) int     g_ecnt[NNODES];
__device__ __align__(16) int     g_incl[NNODES];
__device__ __align__(16) int     g_bsum[SCAN_NB];
__device__ __align__(16) int     g_rowptr[NNODES + 1];
__device__ __align__(16) int     g_cursor[NNODES];
__device__ __align__(16) int     g_col[NEDGES];
__device__ __align__(16) float   g_dinv[NNODES];
__device__ __align__(16) __half2 g_h[NNODES * (FOUT / 2)];   // (x@W)*dinv, fp16 gather table
__device__ __align__(16) float   g_t1[NNODES * FOUT];        // x_temp (residual, fp32)
__device__ __align__(16) float   g_t2[NNODES * FOUT];        // layer-2 activation (fp32)
__device__ int g_is64;

// ---------------- dtype detector ----------------
__global__ void k_detect(const void* __restrict__ ei) {
    const unsigned long long* p = (const unsigned long long*)ei;
    __shared__ unsigned int s;
    if (threadIdx.x == 0) s = 0u;
    __syncthreads();
    unsigned int any = 0u;
    for (int i = threadIdx.x; i < 4096; i += 256)
        any |= (unsigned int)(p[i] >> 32);
    atomicOr(&s, any);
    __syncthreads();
    if (threadIdx.x == 0) g_is64 = (s == 0u) ? 1 : 0;
}

__device__ __forceinline__ int load_idx(const int* __restrict__ ei32, long long pos) {
    if (g_is64) return (int)((const long long*)ei32)[pos];
    return ei32[pos];
}

// ---------------- CSR build ----------------
__global__ void k_zero() {
    int i = blockIdx.x * blockDim.x + threadIdx.x;
    if (i < NNODES) g_ecnt[i] = 0;
}

__global__ void k_count(const int* __restrict__ ei32) {
    int e = blockIdx.x * blockDim.x + threadIdx.x;
    if (e < NEDGES) {
        int d = load_idx(ei32, (long long)NEDGES + e);
        if ((unsigned)d < (unsigned)NNODES) atomicAdd(&g_ecnt[d], 1);
    }
}

__global__ __launch_bounds__(1024) void k_scan1() {
    __shared__ int wsum[32];
    const int i    = blockIdx.x * 1024 + threadIdx.x;
    const int lane = threadIdx.x & 31;
    const int warp = threadIdx.x >> 5;
    int v = (i < NNODES) ? g_ecnt[i] : 0;
    int x = v;
#pragma unroll
    for (int o = 1; o < 32; o <<= 1) {
        int y = __shfl_up_sync(0xffffffffu, x, o);
        if (lane >= o) x += y;
    }
    if (lane == 31) wsum[warp] = x;
    __syncthreads();
    if (warp == 0) {
        int s = wsum[lane];
#pragma unroll
        for (int o = 1; o < 32; o <<= 1) {
            int y = __shfl_up_sync(0xffffffffu, s, o);
            if (lane >= o) s += y;
        }
        wsum[lane] = s;
    }
    __syncthreads();
    int incl = x + (warp > 0 ? wsum[warp - 1] : 0);
    if (i < NNODES) g_incl[i] = incl;
    if (threadIdx.x == 1023) g_bsum[blockIdx.x] = incl;
}

__global__ void k_scan2() {
    __shared__ int s[128];
    const int t = threadIdx.x;
    s[t] = (t < SCAN_NB) ? g_bsum[t] : 0;
    __syncthreads();
    for (int o = 1; o < 128; o <<= 1) {
        int x = s[t];
        int add = (t >= o) ? s[t - o] : 0;
        __syncthreads();
        s[t] = x + add;
        __syncthreads();
    }
    if (t < SCAN_NB) g_bsum[t] = (t == 0) ? 0 : s[t - 1];
    if (t == 0) g_rowptr[NNODES] = s[SCAN_NB - 1];
}

__global__ __launch_bounds__(1024) void k_scan3() {
    const int i = blockIdx.x * 1024 + threadIdx.x;
    if (i < NNODES) {
        int c = g_ecnt[i];
        int start = g_bsum[blockIdx.x] + g_incl[i] - c;
        g_rowptr[i] = start;
        g_cursor[i] = start;
        g_dinv[i]   = rsqrtf((float)(c + 1));
    }
}

__global__ void k_fill(const int* __restrict__ ei32) {
    int e = blockIdx.x * blockDim.x + threadIdx.x;
    if (e < NEDGES) {
        int d = load_idx(ei32, (long long)NEDGES + e);
        int s = load_idx(ei32, e);
        if ((unsigned)d < (unsigned)NNODES && (unsigned)s < (unsigned)NNODES) {
            int p = atomicAdd(&g_cursor[d], 1);
            g_col[p] = s;
        }
    }
}

// ---------------- HMMA GEMM: g_h[n,:] = half((X[n,:] @ W) * dinv[n]) ----------------
// mma.sync m16n8k16 f32.f16.f16.f32 (baseline sm_80 PTX; no 'a' features).
// Block = 256 threads = 8 warps; M-tile = 128 nodes (warp w -> rows 16w..16w+15),
// N = 64 (8 n-tiles/warp), K chunked by 64 (A: 128x72, B: 64x72 halfs in smem).
template <int K, int SEL>
__global__ __launch_bounds__(256) void k_gemm(const float* __restrict__ Xext,
                                              const float* __restrict__ W) {
    __shared__ __align__(16) __half Asm[128 * ASTR];   // ~18.4 KB
    __shared__ __align__(16) __half Bsm[64 * ASTR];    // ~9.2 KB

    const float* X;
    if constexpr (SEL == 0)      X = Xext;
    else if constexpr (SEL == 1) X = g_t1;
    else                         X = g_t2;

    const int tid  = threadIdx.x;
    const int warp = tid >> 5;
    const int lane = tid & 31;
    const int base = blockIdx.x * 128;
    const int wrow = warp * 16;
    const int qrow = lane >> 2;          // 0..7
    const int qk   = (lane & 3) * 2;     // 0,2,4,6

    float acc[8][4];
#pragma unroll
    for (int t = 0; t < 8; t++)
#pragma unroll
        for (int j = 0; j < 4; j++) acc[t][j] = 0.f;

    constexpr int NCH = K / 64;
#pragma unroll
    for (int ch = 0; ch < NCH; ch++) {
        const int kc = ch * 64;
        // stage A: 128 nodes x 64 k, fp32 -> fp16
        for (int i = tid; i < 128 * 64; i += 256) {
            int r = i >> 6, c = i & 63;
            int node = base + r;
            float v = (node < NNODES) ? X[(size_t)node * K + kc + c] : 0.f;
            Asm[r * ASTR + c] = __float2half_rn(v);
        }
        // stage B transposed: Bsm[n][k] = W[kc+k][n]
        for (int i = tid; i < 64 * 64; i += 256) {
            int n = i >> 6, k = i & 63;
            Bsm[n * ASTR + k] = __float2half_rn(W[(size_t)(kc + k) * FOUT + n]);
        }
        __syncthreads();

#pragma unroll
        for (int s = 0; s < 4; s++) {
            const int k0 = s * 16;
            u32 a0 = *(const u32*)&Asm[(wrow + qrow)     * ASTR + k0 + qk];
            u32 a1 = *(const u32*)&Asm[(wrow + qrow + 8) * ASTR + k0 + qk];
            u32 a2 = *(const u32*)&Asm[(wrow + qrow)     * ASTR + k0 + qk + 8];
            u32 a3 = *(const u32*)&Asm[(wrow + qrow + 8) * ASTR + k0 + qk + 8];
#pragma unroll
            for (int t = 0; t < 8; t++) {
                u32 b0 = *(const u32*)&Bsm[(8 * t + qrow) * ASTR + k0 + qk];
                u32 b1 = *(const u32*)&Bsm[(8 * t + qrow) * ASTR + k0 + qk + 8];
                asm volatile(
                    "mma.sync.aligned.m16n8k16.row.col.f32.f16.f16.f32 "
                    "{%0,%1,%2,%3}, {%4,%5,%6,%7}, {%8,%9}, {%0,%1,%2,%3};"
                    : "+f"(acc[t][0]), "+f"(acc[t][1]), "+f"(acc[t][2]), "+f"(acc[t][3])
                    : "r"(a0), "r"(a1), "r"(a2), "r"(a3), "r"(b0), "r"(b1));
            }
        }
        if (ch + 1 < NCH) __syncthreads();
    }

    // epilogue: D row r, cols (lane&3)*2+{0,1} per n-tile; scale by dinv, store half2
    const int nlo = base + wrow + qrow;
    const int nhi = nlo + 8;
    const float dlo = (nlo < NNODES) ? g_dinv[nlo] : 0.f;
    const float dhi = (nhi < NNODES) ? g_dinv[nhi] : 0.f;
    const int cp = lane & 3;   // half2 column index within n-tile (4 pairs)
#pragma unroll
    for (int t = 0; t < 8; t++) {
        int col = t * 4 + cp;
        if (nlo < NNODES)
            g_h[(size_t)nlo * 32 + col] = __floats2half2_rn(acc[t][0] * dlo, acc[t][1] * dlo);
        if (nhi < NNODES)
            g_h[(size_t)nhi * 32 + col] = __floats2half2_rn(acc[t][2] * dhi, acc[t][3] * dhi);
    }
}

// ---------------- aggregation ----------------
// out[i] = f(dinv[i]*(g_h[i] + sum_{src->i} g_h[src]) + bias); g_h is half2.
// MODE 0: identity -> g_t1 | MODE 1: relu -> g_t2 | MODE 2: relu + g_t1 -> ext out
template <int MODE>
__global__ __launch_bounds__(256) void k_agg(const float* __restrict__ bias,
                                             float* __restrict__ outext) {
    const int warp = threadIdx.x >> 5;
    const int lane = threadIdx.x & 31;
    const int node = blockIdx.x * 8 + warp;
    if (node >= NNODES) return;

    float* out;
    if constexpr (MODE == 0)      out = g_t1;
    else if constexpr (MODE == 1) out = g_t2;
    else                          out = outext;

    const int beg = g_rowptr[node];
    const int end = g_rowptr[node + 1];

    float2 acc = __half22float2(g_h[(size_t)node * 32 + lane]);   // self-loop

    int p = beg;
    for (; p + 4 <= end; p += 4) {
        int s0 = g_col[p], s1 = g_col[p + 1], s2 = g_col[p + 2], s3 = g_col[p + 3];
        float2 b0 = __half22float2(g_h[(size_t)s0 * 32 + lane]);
        float2 b1 = __half22float2(g_h[(size_t)s1 * 32 + lane]);
        float2 b2 = __half22float2(g_h[(size_t)s2 * 32 + lane]);
        float2 b3 = __half22float2(g_h[(size_t)s3 * 32 + lane]);
        acc.x += (b0.x + b1.x) + (b2.x + b3.x);
        acc.y += (b0.y + b1.y) + (b2.y + b3.y);
    }
    for (; p < end; p++) {
        int s = g_col[p];
        float2 b = __half22float2(g_h[(size_t)s * 32 + lane]);
        acc.x += b.x; acc.y += b.y;
    }

    const int off = 2 * lane;
    const float di = g_dinv[node];
    float2 bb = *(const float2*)&bias[off];
    float rx = fmaf(di, acc.x, bb.x);
    float ry = fmaf(di, acc.y, bb.y);
    if (MODE >= 1) { rx = fmaxf(rx, 0.f); ry = fmaxf(ry, 0.f); }
    if (MODE == 2) {
        float2 r = *(const float2*)&g_t1[(size_t)node * FOUT + off];
        rx += r.x; ry += r.y;
    }
    *(float2*)&out[(size_t)node * FOUT + off] = make_float2(rx, ry);
}

// ---------------- launch ----------------
extern "C" void kernel_launch(void* const* d_in, const int* in_sizes, int n_in,
                              void* d_out, int out_size) {
    const float* x  = (const float*)d_in[0];
    const int*   ei = (const int*)d_in[1];     // int32 or int64; detected on device
    const float* W0 = (const float*)d_in[2];
    const float* b0 = (const float*)d_in[3];
    const float* Ws = (const float*)d_in[4];
    const float* bs = (const float*)d_in[5];
    float*       out = (float*)d_out;

    const int NB_N = (NNODES + 255) / 256;
    const int NB_E = (NEDGES + 255) / 256;
    const int NB_T = (NNODES + 127) / 128;   // 782 GEMM tiles
    const int NB_A = (NNODES + 7) / 8;       // 12500

    // CSR build (per call; deterministic)
    k_detect<<<1, 256>>>(ei);
    k_zero  <<<NB_N, 256>>>();
    k_count <<<NB_E, 256>>>(ei);
    k_scan1 <<<SCAN_NB, 1024>>>();
    k_scan2 <<<1, 128>>>();
    k_scan3 <<<SCAN_NB, 1024>>>();
    k_fill  <<<NB_E, 256>>>(ei);

    // layer 1: t1 = conv(x, W0, b0)
    k_gemm<FIN, 0> <<<NB_T, 256>>>(x, W0);
    k_agg<0>       <<<NB_A, 256>>>(b0, nullptr);

    // layer 2: t2 = relu(conv(t1, Ws[0], bs[0]))
    k_gemm<FOUT, 1><<<NB_T, 256>>>(nullptr, Ws);
    k_agg<1>       <<<NB_A, 256>>>(bs, nullptr);

    // layer 3: out = relu(conv(t2, Ws[1], bs[1])) + t1
    k_gemm<FOUT, 2><<<NB_T, 256>>>(nullptr, Ws + FOUT * FOUT);
    k_agg<2>       <<<NB_A, 256>>>(bs + FOUT, out);
}